// round 12
// baseline (speedup 1.0000x reference)
#include <cuda_runtime.h>
#include <cuda_bf16.h>
#include <math.h>

#define N_NODES 100000
#define N_EDGES 1600000
#define HID 128
#define NB_SCAN 98   // ceil(100000/1024)

typedef unsigned long long u64;

// ---------------- scratch (device globals; no allocation allowed) ----------------
__device__ float g_h[(size_t)N_NODES * HID];     // h0, then h1 (overwritten in place)
__device__ float g_m[(size_t)N_NODES * HID];     // h @ W_l
__device__ float g_base[(size_t)N_NODES * HID];  // h @ W_r + b
__device__ int   g_deg[N_NODES];
__device__ float g_inv_deg[N_NODES];
__device__ int   g_row_start[N_NODES];
__device__ int   g_cursor[N_NODES];
__device__ int   g_csr_src[N_EDGES];
__device__ int   g_blocksums[NB_SCAN];

// ---------------- packed fp32x2 helpers (dual fp32 FMA per instruction) ----------------
__device__ __forceinline__ u64 pack2(float lo, float hi) {
    u64 r;
    asm("mov.b64 %0, {%1, %2};" : "=l"(r) : "f"(lo), "f"(hi));
    return r;
}
__device__ __forceinline__ void fma2(u64& d, u64 a, u64 b) {
    // d = a * b + d  (two independent IEEE fp32 FMAs, bit-identical to FFMA pair)
    asm("fma.rn.f32x2 %0, %1, %2, %0;" : "+l"(d) : "l"(a), "l"(b));
}

// ---------------- CSR build ----------------
__global__ void k_zero_deg() {
    int i = blockIdx.x * blockDim.x + threadIdx.x;
    if (i < N_NODES) g_deg[i] = 0;
}

__global__ void k_deg(const int* __restrict__ edge) {
    int e = blockIdx.x * blockDim.x + threadIdx.x;
    if (e < N_EDGES) {
        int dst = edge[N_EDGES + e];
        atomicAdd(&g_deg[dst], 1);
    }
}

__global__ void k_scan1() {
    __shared__ int s[1024];
    int tid = threadIdx.x;
    int i = blockIdx.x * 1024 + tid;
    int v = (i < N_NODES) ? g_deg[i] : 0;
    s[tid] = v;
    __syncthreads();
    for (int off = 1; off < 1024; off <<= 1) {
        int t = (tid >= off) ? s[tid - off] : 0;
        __syncthreads();
        s[tid] += t;
        __syncthreads();
    }
    int incl = s[tid];
    if (i < N_NODES) g_row_start[i] = incl - v;  // exclusive within block
    if (tid == 1023) g_blocksums[blockIdx.x] = incl;
}

// parallel 98-element exclusive scan (Hillis-Steele in shared), 128 threads
__global__ void k_scan2() {
    __shared__ int s[128];
    int tid = threadIdx.x;
    int v = (tid < NB_SCAN) ? g_blocksums[tid] : 0;
    s[tid] = v;
    __syncthreads();
#pragma unroll
    for (int off = 1; off < 128; off <<= 1) {
        int t = (tid >= off) ? s[tid - off] : 0;
        __syncthreads();
        s[tid] += t;
        __syncthreads();
    }
    if (tid < NB_SCAN) g_blocksums[tid] = s[tid] - v;  // exclusive
}

__global__ void k_scan3() {
    int i = blockIdx.x * 1024 + threadIdx.x;
    if (i < N_NODES) {
        int rs = g_row_start[i] + g_blocksums[i >> 10];
        g_row_start[i] = rs;
        g_cursor[i] = rs;
        int d = g_deg[i];
        g_inv_deg[i] = 1.0f / fmaxf((float)d, 1.0f);
    }
}

__global__ void k_fill(const int* __restrict__ edge) {
    int e = blockIdx.x * blockDim.x + threadIdx.x;
    if (e < N_EDGES) {
        int src = edge[e];
        int dst = edge[N_EDGES + e];
        int pos = atomicAdd(&g_cursor[dst], 1);
        g_csr_src[pos] = src;
    }
}

// ---------------- feature build: h0 = concat(x, user_emb, loc_emb, time_emb) ----------------
__global__ void k_feat(const float* __restrict__ x,
                       const int* __restrict__ user_ids,
                       const int* __restrict__ locations,
                       const float* __restrict__ time_features,
                       const float* __restrict__ user_emb,
                       const float* __restrict__ loc_emb,
                       const float* __restrict__ W_time,
                       const float* __restrict__ b_time) {
    int warp = threadIdx.x >> 5;
    int lane = threadIdx.x & 31;
    int node = blockIdx.x * 8 + warp;
    if (node >= N_NODES) return;

    float4 v;
    if (lane < 16) {
        v = ((const float4*)(x + (size_t)node * 64))[lane];
    } else if (lane < 24) {
        int uid = user_ids[node];
        v = ((const float4*)(user_emb + (size_t)uid * 32))[lane - 16];
    } else if (lane < 28) {
        int loc = locations[node];
        v = ((const float4*)(loc_emb + (size_t)loc * 16))[lane - 24];
    } else {
        int c0 = (lane - 28) * 4;
        float t0 = time_features[node * 4 + 0];
        float t1 = time_features[node * 4 + 1];
        float t2 = time_features[node * 4 + 2];
        float t3 = time_features[node * 4 + 3];
        float r[4];
#pragma unroll
        for (int j = 0; j < 4; j++) {
            int c = c0 + j;
            r[j] = b_time[c] + t0 * W_time[0 * 16 + c] + t1 * W_time[1 * 16 + c]
                 + t2 * W_time[2 * 16 + c] + t3 * W_time[3 * 16 + c];
        }
        v = make_float4(r[0], r[1], r[2], r[3]);
    }
    ((float4*)(g_h + (size_t)node * HID))[lane] = v;
}

// ---------------- dual GEMM: g_m = h @ W_l ; g_base = h @ W_r + b ----------------
// 512 threads / 16 warps; 4 rows per warp; 64-row tile in 32KB static smem.
// W read via __ldg (L1-resident). Packed fp32x2 FMA: 16 fma2 per k per thread.
__global__ __launch_bounds__(512)
void k_dual_gemm(const float* __restrict__ Wl,
                 const float* __restrict__ Wr,
                 const float* __restrict__ bias) {
    __shared__ float sA[64 * 128];  // 32 KB

    int warp = threadIdx.x >> 5;
    int lane = threadIdx.x & 31;
    int r0 = warp * 4;

    const ulonglong2* Wl2 = (const ulonglong2*)Wl;  // [k*32+lane] = cols 4lane..4lane+3 of row k
    const ulonglong2* Wr2 = (const ulonglong2*)Wr;

    float4 bv = ((const float4*)bias)[lane];
    u64 bias01 = pack2(bv.x, bv.y);
    u64 bias23 = pack2(bv.z, bv.w);

    const int numTiles = (N_NODES + 63) / 64;
    for (int tile = blockIdx.x; tile < numTiles; tile += gridDim.x) {
        int row0 = tile * 64;
        __syncthreads();  // retire previous iteration's readers of sA
        {
            const float4* srcA = (const float4*)(g_h + (size_t)row0 * HID);
            float4* dA = (float4*)sA;
            for (int i = threadIdx.x; i < 64 * 32; i += 512) {
                int r = i >> 5;
                dA[i] = (row0 + r < N_NODES) ? srcA[i] : make_float4(0.f, 0.f, 0.f, 0.f);
            }
        }
        __syncthreads();

        u64 m01[4], m23[4], b01[4], b23[4];
#pragma unroll
        for (int r = 0; r < 4; r++) {
            m01[r] = 0ull;      // (0.f, 0.f)
            m23[r] = 0ull;
            b01[r] = bias01;
            b23[r] = bias23;
        }

#pragma unroll 4
        for (int k = 0; k < 128; k++) {
            ulonglong2 wl = __ldg(&Wl2[k * 32 + lane]);
            ulonglong2 wr = __ldg(&Wr2[k * 32 + lane]);
#pragma unroll
            for (int r = 0; r < 4; r++) {
                float a = sA[(r0 + r) * 128 + k];
                u64 aa = pack2(a, a);
                fma2(m01[r], aa, wl.x);
                fma2(m23[r], aa, wl.y);
                fma2(b01[r], aa, wr.x);
                fma2(b23[r], aa, wr.y);
            }
        }

#pragma unroll
        for (int r = 0; r < 4; r++) {
            int row = row0 + r0 + r;
            if (row < N_NODES) {
                ulonglong2 vm; vm.x = m01[r]; vm.y = m23[r];
                ulonglong2 vb; vb.x = b01[r]; vb.y = b23[r];
                ((ulonglong2*)(g_m + (size_t)row * HID))[lane] = vm;
                ((ulonglong2*)(g_base + (size_t)row * HID))[lane] = vb;
            }
        }
    }
}

// ---------------- aggregation + finish (+ optional fused classifier) ----------------
// one warp per node; lane l owns columns [4l, 4l+4)
template <bool FINAL>
__global__ void k_aggfin(const float* __restrict__ Wc,
                         const float* __restrict__ bc,
                         float* __restrict__ out) {
    int warp = threadIdx.x >> 5;
    int lane = threadIdx.x & 31;
    int node = blockIdx.x * 8 + warp;
    if (node >= N_NODES) return;

    int start = g_row_start[node];
    int d = g_deg[node];
    const float4* mp = (const float4*)g_m;

    float4 acc = make_float4(0.f, 0.f, 0.f, 0.f);
    int e = 0;
    for (; e + 8 <= d; e += 8) {
        int idx[8];
#pragma unroll
        for (int j = 0; j < 8; j++) idx[j] = g_csr_src[start + e + j];
        float4 v[8];
#pragma unroll
        for (int j = 0; j < 8; j++) v[j] = mp[(size_t)idx[j] * 32 + lane];
#pragma unroll
        for (int j = 0; j < 8; j++) {
            acc.x += v[j].x; acc.y += v[j].y; acc.z += v[j].z; acc.w += v[j].w;
        }
    }
    for (; e + 4 <= d; e += 4) {
        int i0 = g_csr_src[start + e + 0];
        int i1 = g_csr_src[start + e + 1];
        int i2 = g_csr_src[start + e + 2];
        int i3 = g_csr_src[start + e + 3];
        float4 v0 = mp[(size_t)i0 * 32 + lane];
        float4 v1 = mp[(size_t)i1 * 32 + lane];
        float4 v2 = mp[(size_t)i2 * 32 + lane];
        float4 v3 = mp[(size_t)i3 * 32 + lane];
        acc.x += (v0.x + v1.x) + (v2.x + v3.x);
        acc.y += (v0.y + v1.y) + (v2.y + v3.y);
        acc.z += (v0.z + v1.z) + (v2.z + v3.z);
        acc.w += (v0.w + v1.w) + (v2.w + v3.w);
    }
    for (; e < d; e++) {
        int i0 = g_csr_src[start + e];
        float4 v0 = mp[(size_t)i0 * 32 + lane];
        acc.x += v0.x; acc.y += v0.y; acc.z += v0.z; acc.w += v0.w;
    }

    float inv = g_inv_deg[node];
    float4 b = ((const float4*)(g_base + (size_t)node * HID))[lane];
    float4 hv;
    hv.x = fmaxf(b.x + acc.x * inv, 0.f);
    hv.y = fmaxf(b.y + acc.y * inv, 0.f);
    hv.z = fmaxf(b.z + acc.z * inv, 0.f);
    hv.w = fmaxf(b.w + acc.w * inv, 0.f);

    if (!FINAL) {
        ((float4*)(g_h + (size_t)node * HID))[lane] = hv;
    } else {
        float p = hv.x * Wc[4 * lane + 0] + hv.y * Wc[4 * lane + 1]
                + hv.z * Wc[4 * lane + 2] + hv.w * Wc[4 * lane + 3];
#pragma unroll
        for (int o = 16; o > 0; o >>= 1) p += __shfl_xor_sync(0xffffffffu, p, o);
        if (lane == 0) {
            float z = p + bc[0];
            out[node] = 1.0f / (1.0f + expf(-z));
        }
    }
}

// ---------------- launch: kernel launches ONLY (graph-capturable) ----------------
extern "C" void kernel_launch(void* const* d_in, const int* in_sizes, int n_in,
                              void* d_out, int out_size) {
    const float* x         = (const float*)d_in[0];
    const int*   edge      = (const int*)d_in[1];
    const int*   user_ids  = (const int*)d_in[2];
    const int*   locations = (const int*)d_in[3];
    const float* time_feat = (const float*)d_in[4];
    const float* user_emb  = (const float*)d_in[5];
    const float* loc_emb   = (const float*)d_in[6];
    const float* W_time    = (const float*)d_in[7];
    const float* b_time    = (const float*)d_in[8];
    const float* W1_l      = (const float*)d_in[9];
    const float* b1        = (const float*)d_in[10];
    const float* W1_r      = (const float*)d_in[11];
    const float* W2_l      = (const float*)d_in[12];
    const float* b2        = (const float*)d_in[13];
    const float* W2_r      = (const float*)d_in[14];
    const float* Wc        = (const float*)d_in[15];
    const float* bc        = (const float*)d_in[16];
    float* out = (float*)d_out;

    // --- CSR build ---
    k_zero_deg<<<(N_NODES + 255) / 256, 256>>>();
    k_deg<<<(N_EDGES + 255) / 256, 256>>>(edge);
    k_scan1<<<NB_SCAN, 1024>>>();
    k_scan2<<<1, 128>>>();
    k_scan3<<<NB_SCAN, 1024>>>();
    k_fill<<<(N_EDGES + 255) / 256, 256>>>(edge);

    // --- features ---
    k_feat<<<(N_NODES + 7) / 8, 256>>>(x, user_ids, locations, time_feat,
                                       user_emb, loc_emb, W_time, b_time);

    // --- layer 1 ---
    k_dual_gemm<<<148, 512>>>(W1_l, W1_r, b1);
    k_aggfin<false><<<(N_NODES + 7) / 8, 256>>>(Wc, bc, out);

    // --- layer 2 + classifier ---
    k_dual_gemm<<<148, 512>>>(W2_l, W2_r, b2);
    k_aggfin<true><<<(N_NODES + 7) / 8, 256>>>(Wc, bc, out);
}

// round 13
// speedup vs baseline: 1.0030x; 1.0030x over previous
#include <cuda_runtime.h>
#include <cuda_bf16.h>
#include <math.h>

#define N_NODES 100000
#define N_EDGES 1600000
#define HID 128
#define NB_SCAN 98   // ceil(100000/1024)

typedef unsigned long long u64;

// ---------------- scratch (device globals; no allocation allowed) ----------------
__device__ float g_h[(size_t)N_NODES * HID];     // h0, then h1 (overwritten in place)
__device__ float g_m[(size_t)N_NODES * HID];     // h @ W_l
__device__ float g_base[(size_t)N_NODES * HID];  // h @ W_r + b
__device__ int   g_deg[N_NODES];
__device__ float g_inv_deg[N_NODES];
__device__ int   g_row_start[N_NODES];
__device__ int   g_cursor[N_NODES];
__device__ int   g_csr_src[N_EDGES];
__device__ int   g_blocksums[NB_SCAN];

// ---------------- packed fp32x2 helpers ----------------
__device__ __forceinline__ u64 pack2(float lo, float hi) {
    u64 r;
    asm("mov.b64 %0, {%1, %2};" : "=l"(r) : "f"(lo), "f"(hi));
    return r;
}
__device__ __forceinline__ void fma2(u64& d, u64 a, u64 b) {
    asm("fma.rn.f32x2 %0, %1, %2, %0;" : "+l"(d) : "l"(a), "l"(b));
}

// ---------------- CSR build ----------------
__global__ void k_zero_deg() {
    int i = blockIdx.x * blockDim.x + threadIdx.x;
    if (i < N_NODES) g_deg[i] = 0;
}

__global__ void k_deg(const int* __restrict__ edge) {
    int e = blockIdx.x * blockDim.x + threadIdx.x;
    if (e < N_EDGES) {
        int dst = edge[N_EDGES + e];
        atomicAdd(&g_deg[dst], 1);
    }
}

__global__ void k_scan1() {
    __shared__ int s[1024];
    int tid = threadIdx.x;
    int i = blockIdx.x * 1024 + tid;
    int v = (i < N_NODES) ? g_deg[i] : 0;
    s[tid] = v;
    __syncthreads();
    for (int off = 1; off < 1024; off <<= 1) {
        int t = (tid >= off) ? s[tid - off] : 0;
        __syncthreads();
        s[tid] += t;
        __syncthreads();
    }
    int incl = s[tid];
    if (i < N_NODES) g_row_start[i] = incl - v;  // exclusive within block
    if (tid == 1023) g_blocksums[blockIdx.x] = incl;
}

// parallel 98-element exclusive scan
__global__ void k_scan2() {
    __shared__ int s[128];
    int tid = threadIdx.x;
    int v = (tid < NB_SCAN) ? g_blocksums[tid] : 0;
    s[tid] = v;
    __syncthreads();
#pragma unroll
    for (int off = 1; off < 128; off <<= 1) {
        int t = (tid >= off) ? s[tid - off] : 0;
        __syncthreads();
        s[tid] += t;
        __syncthreads();
    }
    if (tid < NB_SCAN) g_blocksums[tid] = s[tid] - v;  // exclusive
}

__global__ void k_scan3() {
    int i = blockIdx.x * 1024 + threadIdx.x;
    if (i < N_NODES) {
        int rs = g_row_start[i] + g_blocksums[i >> 10];
        g_row_start[i] = rs;
        g_cursor[i] = rs;
        int d = g_deg[i];
        g_inv_deg[i] = 1.0f / fmaxf((float)d, 1.0f);
    }
}

__global__ void k_fill(const int* __restrict__ edge) {
    int e = blockIdx.x * blockDim.x + threadIdx.x;
    if (e < N_EDGES) {
        int src = edge[e];
        int dst = edge[N_EDGES + e];
        int pos = atomicAdd(&g_cursor[dst], 1);
        g_csr_src[pos] = src;
    }
}

// ---------------- feature build: h0 = concat(x, user_emb, loc_emb, time_emb) ----------------
__global__ void k_feat(const float* __restrict__ x,
                       const int* __restrict__ user_ids,
                       const int* __restrict__ locations,
                       const float* __restrict__ time_features,
                       const float* __restrict__ user_emb,
                       const float* __restrict__ loc_emb,
                       const float* __restrict__ W_time,
                       const float* __restrict__ b_time) {
    int warp = threadIdx.x >> 5;
    int lane = threadIdx.x & 31;
    int node = blockIdx.x * 8 + warp;
    if (node >= N_NODES) return;

    float4 v;
    if (lane < 16) {
        v = ((const float4*)(x + (size_t)node * 64))[lane];
    } else if (lane < 24) {
        int uid = user_ids[node];
        v = ((const float4*)(user_emb + (size_t)uid * 32))[lane - 16];
    } else if (lane < 28) {
        int loc = locations[node];
        v = ((const float4*)(loc_emb + (size_t)loc * 16))[lane - 24];
    } else {
        int c0 = (lane - 28) * 4;
        float t0 = time_features[node * 4 + 0];
        float t1 = time_features[node * 4 + 1];
        float t2 = time_features[node * 4 + 2];
        float t3 = time_features[node * 4 + 3];
        float r[4];
#pragma unroll
        for (int j = 0; j < 4; j++) {
            int c = c0 + j;
            r[j] = b_time[c] + t0 * W_time[0 * 16 + c] + t1 * W_time[1 * 16 + c]
                 + t2 * W_time[2 * 16 + c] + t3 * W_time[3 * 16 + c];
        }
        v = make_float4(r[0], r[1], r[2], r[3]);
    }
    ((float4*)(g_h + (size_t)node * HID))[lane] = v;
}

// ---------------- dual GEMM: g_m = h @ W_l ; g_base = h @ W_r + b ----------------
__global__ __launch_bounds__(512)
void k_dual_gemm(const float* __restrict__ Wl,
                 const float* __restrict__ Wr,
                 const float* __restrict__ bias) {
    __shared__ float sA[64 * 128];  // 32 KB

    int warp = threadIdx.x >> 5;
    int lane = threadIdx.x & 31;
    int r0 = warp * 4;

    const ulonglong2* Wl2 = (const ulonglong2*)Wl;
    const ulonglong2* Wr2 = (const ulonglong2*)Wr;

    float4 bv = ((const float4*)bias)[lane];
    u64 bias01 = pack2(bv.x, bv.y);
    u64 bias23 = pack2(bv.z, bv.w);

    const int numTiles = (N_NODES + 63) / 64;
    for (int tile = blockIdx.x; tile < numTiles; tile += gridDim.x) {
        int row0 = tile * 64;
        __syncthreads();
        {
            const float4* srcA = (const float4*)(g_h + (size_t)row0 * HID);
            float4* dA = (float4*)sA;
            for (int i = threadIdx.x; i < 64 * 32; i += 512) {
                int r = i >> 5;
                dA[i] = (row0 + r < N_NODES) ? srcA[i] : make_float4(0.f, 0.f, 0.f, 0.f);
            }
        }
        __syncthreads();

        u64 m01[4], m23[4], b01[4], b23[4];
#pragma unroll
        for (int r = 0; r < 4; r++) {
            m01[r] = 0ull;
            m23[r] = 0ull;
            b01[r] = bias01;
            b23[r] = bias23;
        }

#pragma unroll 4
        for (int k = 0; k < 128; k++) {
            ulonglong2 wl = __ldg(&Wl2[k * 32 + lane]);
            ulonglong2 wr = __ldg(&Wr2[k * 32 + lane]);
#pragma unroll
            for (int r = 0; r < 4; r++) {
                float a = sA[(r0 + r) * 128 + k];
                u64 aa = pack2(a, a);
                fma2(m01[r], aa, wl.x);
                fma2(m23[r], aa, wl.y);
                fma2(b01[r], aa, wr.x);
                fma2(b23[r], aa, wr.y);
            }
        }

#pragma unroll
        for (int r = 0; r < 4; r++) {
            int row = row0 + r0 + r;
            if (row < N_NODES) {
                ulonglong2 vm; vm.x = m01[r]; vm.y = m23[r];
                ulonglong2 vb; vb.x = b01[r]; vb.y = b23[r];
                ((ulonglong2*)(g_m + (size_t)row * HID))[lane] = vm;
                ((ulonglong2*)(g_base + (size_t)row * HID))[lane] = vb;
            }
        }
    }
}

// ---------------- aggregation + finish (+ optional fused classifier) ----------------
template <bool FINAL>
__global__ void k_aggfin(const float* __restrict__ Wc,
                         const float* __restrict__ bc,
                         float* __restrict__ out) {
    int warp = threadIdx.x >> 5;
    int lane = threadIdx.x & 31;
    int node = blockIdx.x * 8 + warp;
    if (node >= N_NODES) return;

    int start = g_row_start[node];
    int d = g_deg[node];
    const float4* mp = (const float4*)g_m;

    float4 acc = make_float4(0.f, 0.f, 0.f, 0.f);
    int e = 0;
    for (; e + 8 <= d; e += 8) {
        int idx[8];
#pragma unroll
        for (int j = 0; j < 8; j++) idx[j] = g_csr_src[start + e + j];
        float4 v[8];
#pragma unroll
        for (int j = 0; j < 8; j++) v[j] = mp[(size_t)idx[j] * 32 + lane];
#pragma unroll
        for (int j = 0; j < 8; j++) {
            acc.x += v[j].x; acc.y += v[j].y; acc.z += v[j].z; acc.w += v[j].w;
        }
    }
    for (; e + 4 <= d; e += 4) {
        int i0 = g_csr_src[start + e + 0];
        int i1 = g_csr_src[start + e + 1];
        int i2 = g_csr_src[start + e + 2];
        int i3 = g_csr_src[start + e + 3];
        float4 v0 = mp[(size_t)i0 * 32 + lane];
        float4 v1 = mp[(size_t)i1 * 32 + lane];
        float4 v2 = mp[(size_t)i2 * 32 + lane];
        float4 v3 = mp[(size_t)i3 * 32 + lane];
        acc.x += (v0.x + v1.x) + (v2.x + v3.x);
        acc.y += (v0.y + v1.y) + (v2.y + v3.y);
        acc.z += (v0.z + v1.z) + (v2.z + v3.z);
        acc.w += (v0.w + v1.w) + (v2.w + v3.w);
    }
    for (; e < d; e++) {
        int i0 = g_csr_src[start + e];
        float4 v0 = mp[(size_t)i0 * 32 + lane];
        acc.x += v0.x; acc.y += v0.y; acc.z += v0.z; acc.w += v0.w;
    }

    float inv = g_inv_deg[node];
    float4 b = ((const float4*)(g_base + (size_t)node * HID))[lane];
    float4 hv;
    hv.x = fmaxf(b.x + acc.x * inv, 0.f);
    hv.y = fmaxf(b.y + acc.y * inv, 0.f);
    hv.z = fmaxf(b.z + acc.z * inv, 0.f);
    hv.w = fmaxf(b.w + acc.w * inv, 0.f);

    if (!FINAL) {
        ((float4*)(g_h + (size_t)node * HID))[lane] = hv;
    } else {
        float p = hv.x * Wc[4 * lane + 0] + hv.y * Wc[4 * lane + 1]
                + hv.z * Wc[4 * lane + 2] + hv.w * Wc[4 * lane + 3];
#pragma unroll
        for (int o = 16; o > 0; o >>= 1) p += __shfl_xor_sync(0xffffffffu, p, o);
        if (lane == 0) {
            float z = p + bc[0];
            out[node] = 1.0f / (1.0f + expf(-z));
        }
    }
}

// ---------------- launch: kernel launches ONLY (graph-capturable) ----------------
// Submission order steers the ncu -s 5 -c 1 window (lands on submission index 3)
// onto k_dual_gemm. Dependency-safe: gemm1 needs only g_h (k_feat); scans need
// only g_deg (k_deg); agg runs after k_fill.
extern "C" void kernel_launch(void* const* d_in, const int* in_sizes, int n_in,
                              void* d_out, int out_size) {
    const float* x         = (const float*)d_in[0];
    const int*   edge      = (const int*)d_in[1];
    const int*   user_ids  = (const int*)d_in[2];
    const int*   locations = (const int*)d_in[3];
    const float* time_feat = (const float*)d_in[4];
    const float* user_emb  = (const float*)d_in[5];
    const float* loc_emb   = (const float*)d_in[6];
    const float* W_time    = (const float*)d_in[7];
    const float* b_time    = (const float*)d_in[8];
    const float* W1_l      = (const float*)d_in[9];
    const float* b1        = (const float*)d_in[10];
    const float* W1_r      = (const float*)d_in[11];
    const float* W2_l      = (const float*)d_in[12];
    const float* b2        = (const float*)d_in[13];
    const float* W2_r      = (const float*)d_in[14];
    const float* Wc        = (const float*)d_in[15];
    const float* bc        = (const float*)d_in[16];
    float* out = (float*)d_out;

    k_zero_deg<<<(N_NODES + 255) / 256, 256>>>();                          // 0
    k_deg<<<(N_EDGES + 255) / 256, 256>>>(edge);                           // 1
    k_feat<<<(N_NODES + 7) / 8, 256>>>(x, user_ids, locations, time_feat,  // 2
                                       user_emb, loc_emb, W_time, b_time);
    k_dual_gemm<<<148, 512>>>(W1_l, W1_r, b1);                             // 3 <- profiled
    k_scan1<<<NB_SCAN, 1024>>>();                                          // 4
    k_scan2<<<1, 128>>>();                                                 // 5
    k_scan3<<<NB_SCAN, 1024>>>();                                          // 6
    k_fill<<<(N_EDGES + 255) / 256, 256>>>(edge);                          // 7

    k_aggfin<false><<<(N_NODES + 7) / 8, 256>>>(Wc, bc, out);              // 8

    k_dual_gemm<<<148, 512>>>(W2_l, W2_r, b2);                             // 9
    k_aggfin<true><<<(N_NODES + 7) / 8, 256>>>(Wc, bc, out);               // 10
}

// round 14
// speedup vs baseline: 1.4452x; 1.4410x over previous
#include <cuda_runtime.h>
#include <cuda_bf16.h>
#include <math.h>

#define N_NODES 100000
#define N_EDGES 1600000
#define HID 128
#define NB_SCAN 98   // ceil(100000/1024)

typedef unsigned long long u64;

// ---------------- scratch (device globals; no allocation allowed) ----------------
__device__ float g_h[(size_t)N_NODES * HID];     // h0, then h1 (overwritten in place)
__device__ float g_m[(size_t)N_NODES * HID];     // h @ W_l
__device__ float g_base[(size_t)N_NODES * HID];  // h @ W_r + b
__device__ int   g_deg[N_NODES];
__device__ float g_inv_deg[N_NODES];
__device__ int   g_row_start[N_NODES];
__device__ int   g_cursor[N_NODES];
__device__ int   g_csr_src[N_EDGES];
__device__ int   g_blocksums[NB_SCAN];

// ---------------- packed fp32x2 helpers ----------------
__device__ __forceinline__ u64 pack2(float lo, float hi) {
    u64 r;
    asm("mov.b64 %0, {%1, %2};" : "=l"(r) : "f"(lo), "f"(hi));
    return r;
}
__device__ __forceinline__ void fma2(u64& d, u64 a, u64 b) {
    asm("fma.rn.f32x2 %0, %1, %2, %0;" : "+l"(d) : "l"(a), "l"(b));
}

// ---------------- CSR build ----------------
__global__ void k_zero_deg() {
    int i = blockIdx.x * blockDim.x + threadIdx.x;
    if (i < N_NODES) g_deg[i] = 0;
}

__global__ void k_deg(const int* __restrict__ edge) {
    int e = blockIdx.x * blockDim.x + threadIdx.x;
    if (e < N_EDGES) {
        int dst = edge[N_EDGES + e];
        atomicAdd(&g_deg[dst], 1);
    }
}

__global__ void k_scan1() {
    __shared__ int s[1024];
    int tid = threadIdx.x;
    int i = blockIdx.x * 1024 + tid;
    int v = (i < N_NODES) ? g_deg[i] : 0;
    s[tid] = v;
    __syncthreads();
    for (int off = 1; off < 1024; off <<= 1) {
        int t = (tid >= off) ? s[tid - off] : 0;
        __syncthreads();
        s[tid] += t;
        __syncthreads();
    }
    int incl = s[tid];
    if (i < N_NODES) g_row_start[i] = incl - v;  // exclusive within block
    if (tid == 1023) g_blocksums[blockIdx.x] = incl;
}

// parallel 98-element exclusive scan
__global__ void k_scan2() {
    __shared__ int s[128];
    int tid = threadIdx.x;
    int v = (tid < NB_SCAN) ? g_blocksums[tid] : 0;
    s[tid] = v;
    __syncthreads();
#pragma unroll
    for (int off = 1; off < 128; off <<= 1) {
        int t = (tid >= off) ? s[tid - off] : 0;
        __syncthreads();
        s[tid] += t;
        __syncthreads();
    }
    if (tid < NB_SCAN) g_blocksums[tid] = s[tid] - v;  // exclusive
}

__global__ void k_scan3() {
    int i = blockIdx.x * 1024 + threadIdx.x;
    if (i < N_NODES) {
        int rs = g_row_start[i] + g_blocksums[i >> 10];
        g_row_start[i] = rs;
        g_cursor[i] = rs;
        int d = g_deg[i];
        g_inv_deg[i] = 1.0f / fmaxf((float)d, 1.0f);
    }
}

__global__ void k_fill(const int* __restrict__ edge) {
    int e = blockIdx.x * blockDim.x + threadIdx.x;
    if (e < N_EDGES) {
        int src = edge[e];
        int dst = edge[N_EDGES + e];
        int pos = atomicAdd(&g_cursor[dst], 1);
        g_csr_src[pos] = src;
    }
}

// ---------------- feature build: h0 = concat(x, user_emb, loc_emb, time_emb) ----------------
__global__ void k_feat(const float* __restrict__ x,
                       const int* __restrict__ user_ids,
                       const int* __restrict__ locations,
                       const float* __restrict__ time_features,
                       const float* __restrict__ user_emb,
                       const float* __restrict__ loc_emb,
                       const float* __restrict__ W_time,
                       const float* __restrict__ b_time) {
    int warp = threadIdx.x >> 5;
    int lane = threadIdx.x & 31;
    int node = blockIdx.x * 8 + warp;
    if (node >= N_NODES) return;

    float4 v;
    if (lane < 16) {
        v = ((const float4*)(x + (size_t)node * 64))[lane];
    } else if (lane < 24) {
        int uid = user_ids[node];
        v = ((const float4*)(user_emb + (size_t)uid * 32))[lane - 16];
    } else if (lane < 28) {
        int loc = locations[node];
        v = ((const float4*)(loc_emb + (size_t)loc * 16))[lane - 24];
    } else {
        int c0 = (lane - 28) * 4;
        float t0 = time_features[node * 4 + 0];
        float t1 = time_features[node * 4 + 1];
        float t2 = time_features[node * 4 + 2];
        float t3 = time_features[node * 4 + 3];
        float r[4];
#pragma unroll
        for (int j = 0; j < 4; j++) {
            int c = c0 + j;
            r[j] = b_time[c] + t0 * W_time[0 * 16 + c] + t1 * W_time[1 * 16 + c]
                 + t2 * W_time[2 * 16 + c] + t3 * W_time[3 * 16 + c];
        }
        v = make_float4(r[0], r[1], r[2], r[3]);
    }
    ((float4*)(g_h + (size_t)node * HID))[lane] = v;
}

// ---------------- dual GEMM: g_m = h @ W_l ; g_base = h @ W_r + b ----------------
// 256 threads / 8 warps; 8 rows per warp; 64-row tile; 2 blocks per SM.
// W staged 4 k-steps at a time via __ldg (halved L1 traffic per row vs 4-row/warp);
// A read via LDS.128 broadcast per 4-k group.
__global__ __launch_bounds__(256, 2)
void k_dual_gemm(const float* __restrict__ Wl,
                 const float* __restrict__ Wr,
                 const float* __restrict__ bias) {
    __shared__ float sA[64 * 128];  // 32 KB

    int warp = threadIdx.x >> 5;   // 0..7
    int lane = threadIdx.x & 31;
    int r0 = warp * 8;

    const ulonglong2* Wl2 = (const ulonglong2*)Wl;  // [k*32+lane] = cols 4lane..4lane+3 of row k
    const ulonglong2* Wr2 = (const ulonglong2*)Wr;

    float4 bv = ((const float4*)bias)[lane];
    u64 bias01 = pack2(bv.x, bv.y);
    u64 bias23 = pack2(bv.z, bv.w);

    const int numTiles = (N_NODES + 63) / 64;
    for (int tile = blockIdx.x; tile < numTiles; tile += gridDim.x) {
        int row0 = tile * 64;
        __syncthreads();  // retire previous iteration's readers of sA
        {
            const float4* srcA = (const float4*)(g_h + (size_t)row0 * HID);
            float4* dA = (float4*)sA;
            for (int i = threadIdx.x; i < 64 * 32; i += 256) {
                int r = i >> 5;
                dA[i] = (row0 + r < N_NODES) ? srcA[i] : make_float4(0.f, 0.f, 0.f, 0.f);
            }
        }
        __syncthreads();

        u64 m01[8], m23[8], b01[8], b23[8];
#pragma unroll
        for (int r = 0; r < 8; r++) {
            m01[r] = 0ull;
            m23[r] = 0ull;
            b01[r] = bias01;
            b23[r] = bias23;
        }

        for (int k4 = 0; k4 < 128; k4 += 4) {
            // stage W for 4 k-steps (8 LDG.128 in flight)
            ulonglong2 wl0 = __ldg(&Wl2[(k4 + 0) * 32 + lane]);
            ulonglong2 wl1 = __ldg(&Wl2[(k4 + 1) * 32 + lane]);
            ulonglong2 wl2 = __ldg(&Wl2[(k4 + 2) * 32 + lane]);
            ulonglong2 wl3 = __ldg(&Wl2[(k4 + 3) * 32 + lane]);
            ulonglong2 wr0 = __ldg(&Wr2[(k4 + 0) * 32 + lane]);
            ulonglong2 wr1 = __ldg(&Wr2[(k4 + 1) * 32 + lane]);
            ulonglong2 wr2 = __ldg(&Wr2[(k4 + 2) * 32 + lane]);
            ulonglong2 wr3 = __ldg(&Wr2[(k4 + 3) * 32 + lane]);
#pragma unroll
            for (int r = 0; r < 8; r++) {
                float4 a4 = *(const float4*)&sA[(r0 + r) * 128 + k4];  // broadcast LDS.128
                u64 aa;
                aa = pack2(a4.x, a4.x);
                fma2(m01[r], aa, wl0.x); fma2(m23[r], aa, wl0.y);
                fma2(b01[r], aa, wr0.x); fma2(b23[r], aa, wr0.y);
                aa = pack2(a4.y, a4.y);
                fma2(m01[r], aa, wl1.x); fma2(m23[r], aa, wl1.y);
                fma2(b01[r], aa, wr1.x); fma2(b23[r], aa, wr1.y);
                aa = pack2(a4.z, a4.z);
                fma2(m01[r], aa, wl2.x); fma2(m23[r], aa, wl2.y);
                fma2(b01[r], aa, wr2.x); fma2(b23[r], aa, wr2.y);
                aa = pack2(a4.w, a4.w);
                fma2(m01[r], aa, wl3.x); fma2(m23[r], aa, wl3.y);
                fma2(b01[r], aa, wr3.x); fma2(b23[r], aa, wr3.y);
            }
        }

#pragma unroll
        for (int r = 0; r < 8; r++) {
            int row = row0 + r0 + r;
            if (row < N_NODES) {
                ulonglong2 vm; vm.x = m01[r]; vm.y = m23[r];
                ulonglong2 vb; vb.x = b01[r]; vb.y = b23[r];
                ((ulonglong2*)(g_m + (size_t)row * HID))[lane] = vm;
                ((ulonglong2*)(g_base + (size_t)row * HID))[lane] = vb;
            }
        }
    }
}

// ---------------- aggregation + finish (+ optional fused classifier) ----------------
template <bool FINAL>
__global__ void k_aggfin(const float* __restrict__ Wc,
                         const float* __restrict__ bc,
                         float* __restrict__ out) {
    int warp = threadIdx.x >> 5;
    int lane = threadIdx.x & 31;
    int node = blockIdx.x * 8 + warp;
    if (node >= N_NODES) return;

    int start = g_row_start[node];
    int d = g_deg[node];
    const float4* mp = (const float4*)g_m;

    float4 acc = make_float4(0.f, 0.f, 0.f, 0.f);
    int e = 0;
    for (; e + 8 <= d; e += 8) {
        int idx[8];
#pragma unroll
        for (int j = 0; j < 8; j++) idx[j] = g_csr_src[start + e + j];
        float4 v[8];
#pragma unroll
        for (int j = 0; j < 8; j++) v[j] = mp[(size_t)idx[j] * 32 + lane];
#pragma unroll
        for (int j = 0; j < 8; j++) {
            acc.x += v[j].x; acc.y += v[j].y; acc.z += v[j].z; acc.w += v[j].w;
        }
    }
    for (; e + 4 <= d; e += 4) {
        int i0 = g_csr_src[start + e + 0];
        int i1 = g_csr_src[start + e + 1];
        int i2 = g_csr_src[start + e + 2];
        int i3 = g_csr_src[start + e + 3];
        float4 v0 = mp[(size_t)i0 * 32 + lane];
        float4 v1 = mp[(size_t)i1 * 32 + lane];
        float4 v2 = mp[(size_t)i2 * 32 + lane];
        float4 v3 = mp[(size_t)i3 * 32 + lane];
        acc.x += (v0.x + v1.x) + (v2.x + v3.x);
        acc.y += (v0.y + v1.y) + (v2.y + v3.y);
        acc.z += (v0.z + v1.z) + (v2.z + v3.z);
        acc.w += (v0.w + v1.w) + (v2.w + v3.w);
    }
    for (; e < d; e++) {
        int i0 = g_csr_src[start + e];
        float4 v0 = mp[(size_t)i0 * 32 + lane];
        acc.x += v0.x; acc.y += v0.y; acc.z += v0.z; acc.w += v0.w;
    }

    float inv = g_inv_deg[node];
    float4 b = ((const float4*)(g_base + (size_t)node * HID))[lane];
    float4 hv;
    hv.x = fmaxf(b.x + acc.x * inv, 0.f);
    hv.y = fmaxf(b.y + acc.y * inv, 0.f);
    hv.z = fmaxf(b.z + acc.z * inv, 0.f);
    hv.w = fmaxf(b.w + acc.w * inv, 0.f);

    if (!FINAL) {
        ((float4*)(g_h + (size_t)node * HID))[lane] = hv;
    } else {
        float p = hv.x * Wc[4 * lane + 0] + hv.y * Wc[4 * lane + 1]
                + hv.z * Wc[4 * lane + 2] + hv.w * Wc[4 * lane + 3];
#pragma unroll
        for (int o = 16; o > 0; o >>= 1) p += __shfl_xor_sync(0xffffffffu, p, o);
        if (lane == 0) {
            float z = p + bc[0];
            out[node] = 1.0f / (1.0f + expf(-z));
        }
    }
}

// ---------------- launch: kernel launches ONLY (graph-capturable) ----------------
// Submission order keeps k_dual_gemm at index 3 so the ncu -s 5 -c 1 window
// profiles it. Dependency-safe: gemm1 needs only g_h (k_feat); scans need
// only g_deg (k_deg); agg runs after k_fill.
extern "C" void kernel_launch(void* const* d_in, const int* in_sizes, int n_in,
                              void* d_out, int out_size) {
    const float* x         = (const float*)d_in[0];
    const int*   edge      = (const int*)d_in[1];
    const int*   user_ids  = (const int*)d_in[2];
    const int*   locations = (const int*)d_in[3];
    const float* time_feat = (const float*)d_in[4];
    const float* user_emb  = (const float*)d_in[5];
    const float* loc_emb   = (const float*)d_in[6];
    const float* W_time    = (const float*)d_in[7];
    const float* b_time    = (const float*)d_in[8];
    const float* W1_l      = (const float*)d_in[9];
    const float* b1        = (const float*)d_in[10];
    const float* W1_r      = (const float*)d_in[11];
    const float* W2_l      = (const float*)d_in[12];
    const float* b2        = (const float*)d_in[13];
    const float* W2_r      = (const float*)d_in[14];
    const float* Wc        = (const float*)d_in[15];
    const float* bc        = (const float*)d_in[16];
    float* out = (float*)d_out;

    k_zero_deg<<<(N_NODES + 255) / 256, 256>>>();                          // 0
    k_deg<<<(N_EDGES + 255) / 256, 256>>>(edge);                           // 1
    k_feat<<<(N_NODES + 7) / 8, 256>>>(x, user_ids, locations, time_feat,  // 2
                                       user_emb, loc_emb, W_time, b_time);
    k_dual_gemm<<<296, 256>>>(W1_l, W1_r, b1);                             // 3 <- profiled
    k_scan1<<<NB_SCAN, 1024>>>();                                          // 4
    k_scan2<<<1, 128>>>();                                                 // 5
    k_scan3<<<NB_SCAN, 1024>>>();                                          // 6
    k_fill<<<(N_EDGES + 255) / 256, 256>>>(edge);                          // 7

    k_aggfin<false><<<(N_NODES + 7) / 8, 256>>>(Wc, bc, out);              // 8

    k_dual_gemm<<<296, 256>>>(W2_l, W2_r, b2);                             // 9
    k_aggfin<true><<<(N_NODES + 7) / 8, 256>>>(Wc, bc, out);               // 10
}